// round 8
// baseline (speedup 1.0000x reference)
#include <cuda_runtime.h>
#include <cuda_bf16.h>

#define N_NODES 100000
#define N_EDGES 3200000
#define IN_CH   256

// Scratch (device globals: allocation APIs are forbidden)
__device__ float g_xm[N_NODES];    // x @ W_mlp
__device__ float g_xl[N_NODES];    // x @ W_lin
__device__ float g_xw[N_NODES];    // x @ W_gcn
__device__ float g_degf[N_NODES];  // in-degree (float, exact: deg << 2^24)
__device__ float g_h[N_NODES];     // rsqrt(deg+1) * xw
__device__ float g_gcn[N_NODES];   // accumulates sum_s h[s]

#define DOT_BLOCKS 592
#define DOT_WARPS  (DOT_BLOCKS * 8)          // 4736
#define NPI 6                                 // nodes per warp-iteration
#define EQUADS     (N_EDGES / 4)              // 800000 int4 groups
#define E16        (N_EDGES / 16)             // 200000 (msg: 4 int4/thread)
#define MSG_BLOCKS ((E16 + 255) / 256)        // 782
#define DEG_BLOCKS ((EQUADS / 2 + 255) / 256) // deg: 8 edges/thread -> 1563

// ---------------------------------------------------------------------------
// Fused kernel: blocks [0,DOT_BLOCKS) = dots (warp/node, 6-node ILP);
// the rest = degree count (8 edges/thread).
__global__ void __launch_bounds__(256) fused_dots_deg_kernel(
        const float* __restrict__ x,
        const float* __restrict__ Wm,
        const float* __restrict__ Wl,
        const float* __restrict__ Wg,
        const int*   __restrict__ dst) {
    if (blockIdx.x < DOT_BLOCKS) {
        int wid  = (blockIdx.x * 256 + threadIdx.x) >> 5;
        int lane = threadIdx.x & 31;
        int i0 = lane, i1 = lane + 32;

        const float4* wm4 = (const float4*)Wm;
        const float4* wl4 = (const float4*)Wl;
        const float4* wg4 = (const float4*)Wg;
        float4 m0 = __ldg(&wm4[i0]), m1 = __ldg(&wm4[i1]);
        float4 l0 = __ldg(&wl4[i0]), l1 = __ldg(&wl4[i1]);
        float4 g0 = __ldg(&wg4[i0]), g1 = __ldg(&wg4[i1]);

        const int stride = DOT_WARPS;
        for (int n0 = wid; n0 < N_NODES; n0 += NPI * stride) {
            int   nn[NPI];
            bool  ok[NPI];
            float4 a[NPI], b[NPI];
#pragma unroll
            for (int j = 0; j < NPI; j++) {
                nn[j] = n0 + j * stride;
                ok[j] = nn[j] < N_NODES;
                const float4* xp = (const float4*)(x + (size_t)(ok[j] ? nn[j] : n0) * IN_CH);
                a[j] = xp[i0];
                b[j] = xp[i1];
            }

            float sm[NPI], sl[NPI], sg[NPI];
#pragma unroll
            for (int j = 0; j < NPI; j++) {
                sm[j] = a[j].x*m0.x + a[j].y*m0.y + a[j].z*m0.z + a[j].w*m0.w
                      + b[j].x*m1.x + b[j].y*m1.y + b[j].z*m1.z + b[j].w*m1.w;
                sl[j] = a[j].x*l0.x + a[j].y*l0.y + a[j].z*l0.z + a[j].w*l0.w
                      + b[j].x*l1.x + b[j].y*l1.y + b[j].z*l1.z + b[j].w*l1.w;
                sg[j] = a[j].x*g0.x + a[j].y*g0.y + a[j].z*g0.z + a[j].w*g0.w
                      + b[j].x*g1.x + b[j].y*g1.y + b[j].z*g1.z + b[j].w*g1.w;
            }
#pragma unroll
            for (int o = 16; o > 0; o >>= 1) {
#pragma unroll
                for (int j = 0; j < NPI; j++) {
                    sm[j] += __shfl_xor_sync(0xffffffffu, sm[j], o);
                    sl[j] += __shfl_xor_sync(0xffffffffu, sl[j], o);
                    sg[j] += __shfl_xor_sync(0xffffffffu, sg[j], o);
                }
            }
            if (lane == 0) {
#pragma unroll
                for (int j = 0; j < NPI; j++) {
                    if (ok[j]) {
                        g_xm[nn[j]] = sm[j];
                        g_xl[nn[j]] = sl[j];
                        g_xw[nn[j]] = sg[j];
                    }
                }
            }
        }
    } else {
        int t = (blockIdx.x - DOT_BLOCKS) * 256 + threadIdx.x;
        if (t < EQUADS / 2) {
            const int4* d4p = (const int4*)dst;
            int4 a = d4p[t];
            int4 b = d4p[t + EQUADS / 2];
            atomicAdd(&g_degf[a.x], 1.0f);
            atomicAdd(&g_degf[a.y], 1.0f);
            atomicAdd(&g_degf[a.z], 1.0f);
            atomicAdd(&g_degf[a.w], 1.0f);
            atomicAdd(&g_degf[b.x], 1.0f);
            atomicAdd(&g_degf[b.y], 1.0f);
            atomicAdd(&g_degf[b.z], 1.0f);
            atomicAdd(&g_degf[b.w], 1.0f);
        }
    }
}

// ---------------------------------------------------------------------------
// h[n] = rsqrt(deg+1) * xw[n], 4 nodes/thread (float4). N_NODES % 4 == 0.
__global__ void __launch_bounds__(256) h_kernel() {
    int i = blockIdx.x * 256 + threadIdx.x;
    if (i < N_NODES / 4) {
        float4 d = ((const float4*)g_degf)[i];
        float4 w = ((const float4*)g_xw)[i];
        float4 r;
        r.x = rsqrtf(d.x + 1.0f) * w.x;
        r.y = rsqrtf(d.y + 1.0f) * w.y;
        r.z = rsqrtf(d.z + 1.0f) * w.z;
        r.w = rsqrtf(d.w + 1.0f) * w.w;
        ((float4*)g_h)[i] = r;
    }
}

// ---------------------------------------------------------------------------
// Edge messages: gcn[d] += h[s]. 16 edges/thread: 8 index-int4 loads,
// 16 L2 gathers batched, then 16 atomics.
__global__ void __launch_bounds__(256) msg_kernel(const int* __restrict__ src,
                                                  const int* __restrict__ dst) {
    int t = blockIdx.x * 256 + threadIdx.x;
    if (t >= E16) return;
    const int4* s4p = (const int4*)src;
    const int4* d4p = (const int4*)dst;

    int4 s0 = s4p[t];
    int4 s1 = s4p[t + E16];
    int4 s2 = s4p[t + 2 * E16];
    int4 s3 = s4p[t + 3 * E16];
    int4 d0 = d4p[t];
    int4 d1 = d4p[t + E16];
    int4 d2 = d4p[t + 2 * E16];
    int4 d3 = d4p[t + 3 * E16];

    float h00 = __ldg(&g_h[s0.x]), h01 = __ldg(&g_h[s0.y]);
    float h02 = __ldg(&g_h[s0.z]), h03 = __ldg(&g_h[s0.w]);
    float h10 = __ldg(&g_h[s1.x]), h11 = __ldg(&g_h[s1.y]);
    float h12 = __ldg(&g_h[s1.z]), h13 = __ldg(&g_h[s1.w]);
    float h20 = __ldg(&g_h[s2.x]), h21 = __ldg(&g_h[s2.y]);
    float h22 = __ldg(&g_h[s2.z]), h23 = __ldg(&g_h[s2.w]);
    float h30 = __ldg(&g_h[s3.x]), h31 = __ldg(&g_h[s3.y]);
    float h32 = __ldg(&g_h[s3.z]), h33 = __ldg(&g_h[s3.w]);

    atomicAdd(&g_gcn[d0.x], h00); atomicAdd(&g_gcn[d0.y], h01);
    atomicAdd(&g_gcn[d0.z], h02); atomicAdd(&g_gcn[d0.w], h03);
    atomicAdd(&g_gcn[d1.x], h10); atomicAdd(&g_gcn[d1.y], h11);
    atomicAdd(&g_gcn[d1.z], h12); atomicAdd(&g_gcn[d1.w], h13);
    atomicAdd(&g_gcn[d2.x], h20); atomicAdd(&g_gcn[d2.y], h21);
    atomicAdd(&g_gcn[d2.z], h22); atomicAdd(&g_gcn[d2.w], h23);
    atomicAdd(&g_gcn[d3.x], h30); atomicAdd(&g_gcn[d3.y], h31);
    atomicAdd(&g_gcn[d3.z], h32); atomicAdd(&g_gcn[d3.w], h33);
}

__device__ __forceinline__ float sigmoidf_(float v) {
    return 1.0f / (1.0f + expf(-v));
}

__device__ __forceinline__ float fitness1(float degf, float xm, float xl,
                                          float gcnacc, float hv,
                                          float alpha, float beta,
                                          const float* W_att, const float* b_att) {
    float dinv = rsqrtf(degf + 1.0f);
    float gcn  = dinv * (gcnacc + hv);      // h = dinv*xw
    float s1 = sigmoidf_(alpha * sqrtf(degf) + beta);
    float s2 = sigmoidf_(xm);
    float s3 = sigmoidf_(gcn + xl);
    float l0 = s1 * __ldg(&W_att[0]) + s2 * __ldg(&W_att[1]) + s3 * __ldg(&W_att[2]) + __ldg(&b_att[0]);
    float l1 = s1 * __ldg(&W_att[3]) + s2 * __ldg(&W_att[4]) + s3 * __ldg(&W_att[5]) + __ldg(&b_att[1]);
    float l2 = s1 * __ldg(&W_att[6]) + s2 * __ldg(&W_att[7]) + s3 * __ldg(&W_att[8]) + __ldg(&b_att[2]);
    float m  = fmaxf(l0, fmaxf(l1, l2));
    float e0 = expf(l0 - m), e1 = expf(l1 - m), e2 = expf(l2 - m);
    float inv = 1.0f / (e0 + e1 + e2);
    return (e0 * s1 + e1 * s2 + e2 * s3) * inv;
}

// Final fusion, 2 nodes/thread via float2 (N_NODES even).
__global__ void __launch_bounds__(256) final_kernel(
        const float* __restrict__ alpha_p,
        const float* __restrict__ beta_p,
        const float* __restrict__ W_att,
        const float* __restrict__ b_att,
        float* __restrict__ out) {
    int i = blockIdx.x * 256 + threadIdx.x;
    if (i >= N_NODES / 2) return;

    float alpha = __ldg(alpha_p);
    float beta  = __ldg(beta_p);

    float2 dg = ((const float2*)g_degf)[i];
    float2 xm = ((const float2*)g_xm)[i];
    float2 xl = ((const float2*)g_xl)[i];
    float2 gc = ((const float2*)g_gcn)[i];
    float2 hv = ((const float2*)g_h)[i];

    float2 r;
    r.x = fitness1(dg.x, xm.x, xl.x, gc.x, hv.x, alpha, beta, W_att, b_att);
    r.y = fitness1(dg.y, xm.y, xl.y, gc.y, hv.y, alpha, beta, W_att, b_att);
    ((float2*)out)[i] = r;
}

// ---------------------------------------------------------------------------
extern "C" void kernel_launch(void* const* d_in, const int* in_sizes, int n_in,
                              void* d_out, int out_size) {
    const float* x     = (const float*)d_in[0];
    const int*   eidx  = (const int*)d_in[1];   // [2, N_EDGES] int32
    const float* alpha = (const float*)d_in[2];
    const float* beta  = (const float*)d_in[3];
    const float* Wm    = (const float*)d_in[4];
    const float* Wl    = (const float*)d_in[5];
    const float* Wg    = (const float*)d_in[6];
    const float* Watt  = (const float*)d_in[7];
    const float* batt  = (const float*)d_in[8];
    float* out = (float*)d_out;

    const int* src = eidx;            // edge_index[0]
    const int* dst = eidx + N_EDGES;  // edge_index[1]

    void *degf_ptr = nullptr, *gcn_ptr = nullptr;
    cudaGetSymbolAddress(&degf_ptr, g_degf);
    cudaGetSymbolAddress(&gcn_ptr,  g_gcn);
    cudaMemsetAsync(degf_ptr, 0, N_NODES * sizeof(float));
    cudaMemsetAsync(gcn_ptr,  0, N_NODES * sizeof(float));

    fused_dots_deg_kernel<<<DOT_BLOCKS + DEG_BLOCKS, 256>>>(x, Wm, Wl, Wg, dst);
    h_kernel<<<(N_NODES / 4 + 255) / 256, 256>>>();
    msg_kernel<<<MSG_BLOCKS, 256>>>(src, dst);
    final_kernel<<<(N_NODES / 2 + 255) / 256, 256>>>(alpha, beta, Watt, batt, out);
}

// round 9
// speedup vs baseline: 1.0340x; 1.0340x over previous
#include <cuda_runtime.h>
#include <cuda_bf16.h>

#define N_NODES 100000
#define N_EDGES 3200000
#define IN_CH   256

// Scratch (device globals: allocation APIs are forbidden)
__device__ float g_xm[N_NODES];    // x @ W_mlp
__device__ float g_xl[N_NODES];    // x @ W_lin
__device__ float g_xw[N_NODES];    // x @ W_gcn
__device__ float g_degf[N_NODES];  // in-degree (float, exact: deg << 2^24)
__device__ float g_h[N_NODES];     // rsqrt(deg+1) * xw
__device__ float g_gcn[N_NODES];   // accumulates sum_s h[s]

#define DOT_BLOCKS 592
#define DOT_WARPS  (DOT_BLOCKS * 8)        // 4736
#define EQUADS     (N_EDGES / 4)           // 800000 int4 groups
#define EGROUPS    (N_EDGES / 8)           // 400000 (8 edges per thread)
#define EDG_BLOCKS ((EGROUPS + 255) / 256) // 1563

// Side stream + fork/join events, created once at static init (streams and
// events are driver objects, not device-memory allocations).
struct SideStream {
    cudaStream_t s1;
    cudaEvent_t  evFork, evJoin;
    SideStream() {
        cudaStreamCreateWithFlags(&s1, cudaStreamNonBlocking);
        cudaEventCreateWithFlags(&evFork, cudaEventDisableTiming);
        cudaEventCreateWithFlags(&evJoin, cudaEventDisableTiming);
    }
};
static SideStream g_ss;

// ---------------------------------------------------------------------------
__device__ __forceinline__ void dot3(const float4 a0, const float4 a1,
                                     const float4 m0, const float4 m1,
                                     const float4 l0, const float4 l1,
                                     const float4 g0, const float4 g1,
                                     float& sm, float& sl, float& sg) {
    sm = a0.x*m0.x + a0.y*m0.y + a0.z*m0.z + a0.w*m0.w
       + a1.x*m1.x + a1.y*m1.y + a1.z*m1.z + a1.w*m1.w;
    sl = a0.x*l0.x + a0.y*l0.y + a0.z*l0.z + a0.w*l0.w
       + a1.x*l1.x + a1.y*l1.y + a1.z*l1.z + a1.w*l1.w;
    sg = a0.x*g0.x + a0.y*g0.y + a0.z*g0.z + a0.w*g0.w
       + a1.x*g1.x + a1.y*g1.y + a1.z*g1.z + a1.w*g1.w;
}

// Dots: warp per node, 4 nodes per iteration, weights in registers,
// streaming (__ldcs) x loads.
__global__ void __launch_bounds__(256) dots_kernel(
        const float* __restrict__ x,
        const float* __restrict__ Wm,
        const float* __restrict__ Wl,
        const float* __restrict__ Wg) {
    int wid  = (blockIdx.x * 256 + threadIdx.x) >> 5;
    int lane = threadIdx.x & 31;
    int i0 = lane, i1 = lane + 32;

    const float4* wm4 = (const float4*)Wm;
    const float4* wl4 = (const float4*)Wl;
    const float4* wg4 = (const float4*)Wg;
    float4 m0 = __ldg(&wm4[i0]), m1 = __ldg(&wm4[i1]);
    float4 l0 = __ldg(&wl4[i0]), l1 = __ldg(&wl4[i1]);
    float4 g0 = __ldg(&wg4[i0]), g1 = __ldg(&wg4[i1]);

    const int stride = DOT_WARPS;
    for (int n0 = wid; n0 < N_NODES; n0 += 4 * stride) {
        int n1 = n0 + stride;
        int n2 = n0 + 2 * stride;
        int n3 = n0 + 3 * stride;
        bool h1 = n1 < N_NODES, h2 = n2 < N_NODES, h3 = n3 < N_NODES;

        const float4* x0 = (const float4*)(x + (size_t)n0 * IN_CH);
        const float4* x1 = (const float4*)(x + (size_t)(h1 ? n1 : n0) * IN_CH);
        const float4* x2 = (const float4*)(x + (size_t)(h2 ? n2 : n0) * IN_CH);
        const float4* x3 = (const float4*)(x + (size_t)(h3 ? n3 : n0) * IN_CH);

        float4 a0 = __ldcs(&x0[i0]), a1 = __ldcs(&x0[i1]);
        float4 b0 = __ldcs(&x1[i0]), b1 = __ldcs(&x1[i1]);
        float4 c0 = __ldcs(&x2[i0]), c1 = __ldcs(&x2[i1]);
        float4 d0 = __ldcs(&x3[i0]), d1 = __ldcs(&x3[i1]);

        float smA, slA, sgA, smB, slB, sgB, smC, slC, sgC, smD, slD, sgD;
        dot3(a0, a1, m0, m1, l0, l1, g0, g1, smA, slA, sgA);
        dot3(b0, b1, m0, m1, l0, l1, g0, g1, smB, slB, sgB);
        dot3(c0, c1, m0, m1, l0, l1, g0, g1, smC, slC, sgC);
        dot3(d0, d1, m0, m1, l0, l1, g0, g1, smD, slD, sgD);

#pragma unroll
        for (int o = 16; o > 0; o >>= 1) {
            smA += __shfl_xor_sync(0xffffffffu, smA, o);
            slA += __shfl_xor_sync(0xffffffffu, slA, o);
            sgA += __shfl_xor_sync(0xffffffffu, sgA, o);
            smB += __shfl_xor_sync(0xffffffffu, smB, o);
            slB += __shfl_xor_sync(0xffffffffu, slB, o);
            sgB += __shfl_xor_sync(0xffffffffu, sgB, o);
            smC += __shfl_xor_sync(0xffffffffu, smC, o);
            slC += __shfl_xor_sync(0xffffffffu, slC, o);
            sgC += __shfl_xor_sync(0xffffffffu, sgC, o);
            smD += __shfl_xor_sync(0xffffffffu, smD, o);
            slD += __shfl_xor_sync(0xffffffffu, slD, o);
            sgD += __shfl_xor_sync(0xffffffffu, sgD, o);
        }
        if (lane == 0) {
            g_xm[n0] = smA; g_xl[n0] = slA; g_xw[n0] = sgA;
            if (h1) { g_xm[n1] = smB; g_xl[n1] = slB; g_xw[n1] = sgB; }
            if (h2) { g_xm[n2] = smC; g_xl[n2] = slC; g_xw[n2] = sgC; }
            if (h3) { g_xm[n3] = smD; g_xl[n3] = slD; g_xw[n3] = sgD; }
        }
    }
}

// ---------------------------------------------------------------------------
// Degree count: 8 edges/thread (runs on the side stream, parallel with dots).
__global__ void __launch_bounds__(256) deg_kernel(const int* __restrict__ dst) {
    int t = blockIdx.x * 256 + threadIdx.x;
    if (t >= EGROUPS) return;
    const int4* d4p = (const int4*)dst;
    int4 a = d4p[t];
    int4 b = d4p[t + EGROUPS];
    atomicAdd(&g_degf[a.x], 1.0f);
    atomicAdd(&g_degf[a.y], 1.0f);
    atomicAdd(&g_degf[a.z], 1.0f);
    atomicAdd(&g_degf[a.w], 1.0f);
    atomicAdd(&g_degf[b.x], 1.0f);
    atomicAdd(&g_degf[b.y], 1.0f);
    atomicAdd(&g_degf[b.z], 1.0f);
    atomicAdd(&g_degf[b.w], 1.0f);
}

// ---------------------------------------------------------------------------
// h[n] = rsqrt(deg+1) * xw[n], 4 nodes/thread (N_NODES % 4 == 0).
__global__ void __launch_bounds__(256) h_kernel() {
    int i = blockIdx.x * 256 + threadIdx.x;
    if (i < N_NODES / 4) {
        float4 d = ((const float4*)g_degf)[i];
        float4 w = ((const float4*)g_xw)[i];
        float4 r;
        r.x = rsqrtf(d.x + 1.0f) * w.x;
        r.y = rsqrtf(d.y + 1.0f) * w.y;
        r.z = rsqrtf(d.z + 1.0f) * w.z;
        r.w = rsqrtf(d.w + 1.0f) * w.w;
        ((float4*)g_h)[i] = r;
    }
}

// ---------------------------------------------------------------------------
// Edge messages: gcn[d] += h[s]. 8 edges/thread, gathers batched.
__global__ void __launch_bounds__(256) msg_kernel(const int* __restrict__ src,
                                                  const int* __restrict__ dst) {
    int t = blockIdx.x * 256 + threadIdx.x;
    if (t >= EGROUPS) return;
    const int4* s4p = (const int4*)src;
    const int4* d4p = (const int4*)dst;
    int4 sa = s4p[t];
    int4 sb = s4p[t + EGROUPS];
    int4 da = d4p[t];
    int4 db = d4p[t + EGROUPS];

    float h0 = __ldg(&g_h[sa.x]);
    float h1 = __ldg(&g_h[sa.y]);
    float h2 = __ldg(&g_h[sa.z]);
    float h3 = __ldg(&g_h[sa.w]);
    float h4 = __ldg(&g_h[sb.x]);
    float h5 = __ldg(&g_h[sb.y]);
    float h6 = __ldg(&g_h[sb.z]);
    float h7 = __ldg(&g_h[sb.w]);

    atomicAdd(&g_gcn[da.x], h0);
    atomicAdd(&g_gcn[da.y], h1);
    atomicAdd(&g_gcn[da.z], h2);
    atomicAdd(&g_gcn[da.w], h3);
    atomicAdd(&g_gcn[db.x], h4);
    atomicAdd(&g_gcn[db.y], h5);
    atomicAdd(&g_gcn[db.z], h6);
    atomicAdd(&g_gcn[db.w], h7);
}

// ---------------------------------------------------------------------------
__device__ __forceinline__ float fsigmoid(float v) {
    return 1.0f / (1.0f + __expf(-v));
}

__device__ __forceinline__ float fitness1(float degf, float xm, float xl,
                                          float gcnacc, float hv,
                                          float alpha, float beta,
                                          const float* W_att, const float* b_att) {
    float dinv = rsqrtf(degf + 1.0f);
    float gcn  = dinv * (gcnacc + hv);      // h = dinv*xw
    float s1 = fsigmoid(alpha * sqrtf(degf) + beta);
    float s2 = fsigmoid(xm);
    float s3 = fsigmoid(gcn + xl);
    float l0 = s1 * __ldg(&W_att[0]) + s2 * __ldg(&W_att[1]) + s3 * __ldg(&W_att[2]) + __ldg(&b_att[0]);
    float l1 = s1 * __ldg(&W_att[3]) + s2 * __ldg(&W_att[4]) + s3 * __ldg(&W_att[5]) + __ldg(&b_att[1]);
    float l2 = s1 * __ldg(&W_att[6]) + s2 * __ldg(&W_att[7]) + s3 * __ldg(&W_att[8]) + __ldg(&b_att[2]);
    float m  = fmaxf(l0, fmaxf(l1, l2));
    float e0 = __expf(l0 - m), e1 = __expf(l1 - m), e2 = __expf(l2 - m);
    float inv = 1.0f / (e0 + e1 + e2);
    return (e0 * s1 + e1 * s2 + e2 * s3) * inv;
}

// Final fusion, 2 nodes/thread (N_NODES even).
__global__ void __launch_bounds__(256) final_kernel(
        const float* __restrict__ alpha_p,
        const float* __restrict__ beta_p,
        const float* __restrict__ W_att,
        const float* __restrict__ b_att,
        float* __restrict__ out) {
    int i = blockIdx.x * 256 + threadIdx.x;
    if (i >= N_NODES / 2) return;

    float alpha = __ldg(alpha_p);
    float beta  = __ldg(beta_p);

    float2 dg = ((const float2*)g_degf)[i];
    float2 xm = ((const float2*)g_xm)[i];
    float2 xl = ((const float2*)g_xl)[i];
    float2 gc = ((const float2*)g_gcn)[i];
    float2 hv = ((const float2*)g_h)[i];

    float2 r;
    r.x = fitness1(dg.x, xm.x, xl.x, gc.x, hv.x, alpha, beta, W_att, b_att);
    r.y = fitness1(dg.y, xm.y, xl.y, gc.y, hv.y, alpha, beta, W_att, b_att);
    ((float2*)out)[i] = r;
}

// ---------------------------------------------------------------------------
extern "C" void kernel_launch(void* const* d_in, const int* in_sizes, int n_in,
                              void* d_out, int out_size) {
    const float* x     = (const float*)d_in[0];
    const int*   eidx  = (const int*)d_in[1];   // [2, N_EDGES] int32
    const float* alpha = (const float*)d_in[2];
    const float* beta  = (const float*)d_in[3];
    const float* Wm    = (const float*)d_in[4];
    const float* Wl    = (const float*)d_in[5];
    const float* Wg    = (const float*)d_in[6];
    const float* Watt  = (const float*)d_in[7];
    const float* batt  = (const float*)d_in[8];
    float* out = (float*)d_out;

    const int* src = eidx;            // edge_index[0]
    const int* dst = eidx + N_EDGES;  // edge_index[1]

    void *degf_ptr = nullptr, *gcn_ptr = nullptr;
    cudaGetSymbolAddress(&degf_ptr, g_degf);
    cudaGetSymbolAddress(&gcn_ptr,  g_gcn);
    cudaMemsetAsync(degf_ptr, 0, N_NODES * sizeof(float), 0);
    cudaMemsetAsync(gcn_ptr,  0, N_NODES * sizeof(float), 0);

    // Fork: deg runs on side stream, concurrent with dots on the main stream.
    cudaEventRecord(g_ss.evFork, 0);
    cudaStreamWaitEvent(g_ss.s1, g_ss.evFork, 0);
    deg_kernel<<<EDG_BLOCKS, 256, 0, g_ss.s1>>>(dst);
    cudaEventRecord(g_ss.evJoin, g_ss.s1);

    dots_kernel<<<DOT_BLOCKS, 256>>>(x, Wm, Wl, Wg);

    // Join: h needs both degf (side) and xw (main).
    cudaStreamWaitEvent(0, g_ss.evJoin, 0);

    h_kernel<<<(N_NODES / 4 + 255) / 256, 256>>>();
    msg_kernel<<<EDG_BLOCKS, 256>>>(src, dst);
    final_kernel<<<(N_NODES / 2 + 255) / 256, 256>>>(alpha, beta, Watt, batt, out);
}